// round 10
// baseline (speedup 1.0000x reference)
#include <cuda_runtime.h>

#define N_CELL  50000
#define N_NET   10000
#define N_GCELL 20000
#define NE      100000
#define D       32
#define DPF     16
#define GP      17           // DPF + 1 (bias row)
#define TSRC    16           // source nodes per fused-nnconv block
#define NB_NET_NN (N_NET / TSRC)     // 625
#define NB_GC_NN  (N_GCELL / TSRC)   // 1250
#define CAPN    512          // bin capacity, net side (mean 160)
#define CAPH    256          // bin capacity, gcell side (mean 80)

// ---------------- scratch (static device globals; no allocs) ------------
__device__ __align__(16) float g_agg_net[N_NET * D];
__device__ __align__(16) float g_agg_gc_c[N_GCELL * D];
__device__ __align__(16) float g_agg_gc_pt[N_GCELL * D];
__device__ __align__(16) float g_agg_cell_pd[N_CELL * D];
__device__ __align__(16) float g_agg_cell_pf[N_CELL * D];
__device__ __align__(16) int g_cnt_pins_src[N_CELL];
__device__ __align__(16) int g_cnt_pins_dst[N_NET];
__device__ __align__(16) int g_cnt_pinned_dst[N_CELL];
__device__ __align__(16) int g_cnt_connect_src[N_GCELL];
__device__ __align__(16) int g_cnt_connect_dst[N_GCELL];
__device__ __align__(16) int g_cnt_pt_src[N_CELL];
__device__ __align__(16) int g_cnt_pt_dst[N_GCELL];
__device__ __align__(16) int g_cnt_pf_dst[N_CELL];
__device__ __align__(16) int g_bincnt_net[NB_NET_NN];
__device__ __align__(16) int g_bincnt_han[NB_GC_NN];
__device__ int g_bin_net[NB_NET_NN * CAPN];
__device__ int g_bin_han[NB_GC_NN * CAPH];

// vector reduction to global (sm_90+)
__device__ __forceinline__ void red_add_f4(float* p, float4 v) {
    asm volatile("red.global.add.v4.f32 [%0], {%1,%2,%3,%4};"
                 :: "l"(p), "f"(v.x), "f"(v.y), "f"(v.z), "f"(v.w) : "memory");
}

// ---------------- kernels ----------------

__global__ void k_zero() {
    int tid = blockIdx.x * blockDim.x + threadIdx.x;
    int stride = gridDim.x * blockDim.x;
    float4 z4 = {0.f, 0.f, 0.f, 0.f};
    int4 zi = {0, 0, 0, 0};
    for (int i = tid; i < N_NET * D / 4; i += stride) ((float4*)g_agg_net)[i] = z4;
    for (int i = tid; i < N_GCELL * D / 4; i += stride) { ((float4*)g_agg_gc_c)[i] = z4; ((float4*)g_agg_gc_pt)[i] = z4; }
    for (int i = tid; i < N_CELL * D / 4; i += stride) { ((float4*)g_agg_cell_pd)[i] = z4; ((float4*)g_agg_cell_pf)[i] = z4; }
    for (int i = tid; i < N_CELL / 4; i += stride) {
        ((int4*)g_cnt_pins_src)[i] = zi; ((int4*)g_cnt_pinned_dst)[i] = zi;
        ((int4*)g_cnt_pt_src)[i] = zi;   ((int4*)g_cnt_pf_dst)[i] = zi;
    }
    for (int i = tid; i < N_NET / 4; i += stride) ((int4*)g_cnt_pins_dst)[i] = zi;
    for (int i = tid; i < N_GCELL / 4; i += stride) {
        ((int4*)g_cnt_connect_src)[i] = zi; ((int4*)g_cnt_connect_dst)[i] = zi;
        ((int4*)g_cnt_pt_dst)[i] = zi;
    }
    for (int i = tid; i < NB_NET_NN; i += stride) g_bincnt_net[i] = 0;
    for (int i = tid; i < NB_GC_NN; i += stride) g_bincnt_han[i] = 0;
}

// one fused prep kernel: 10 roles x NE threads; each thread 1 LDG + 1 RED/append.
#define RBLK ((NE + 255) / 256)      // 391 blocks per role
__global__ void k_prep(const int* __restrict__ pins_src, const int* __restrict__ pins_dst,
                       const int* __restrict__ pinned_src, const int* __restrict__ pinned_dst,
                       const int* __restrict__ connect_src, const int* __restrict__ connect_dst,
                       const int* __restrict__ pt_src, const int* __restrict__ pt_dst,
                       const int* __restrict__ pf_src, const int* __restrict__ pf_dst) {
    int role = blockIdx.x / RBLK;
    int e = (blockIdx.x - role * RBLK) * 256 + threadIdx.x;
    if (e >= NE) return;
    switch (role) {
        case 0: atomicAdd(&g_cnt_pins_src[pins_src[e]], 1); break;
        case 1: atomicAdd(&g_cnt_connect_src[connect_src[e]], 1); break;
        case 2: atomicAdd(&g_cnt_pt_src[pt_src[e]], 1); break;
        case 3: atomicAdd(&g_cnt_pins_dst[pins_dst[e]], 1); break;
        case 4: atomicAdd(&g_cnt_pinned_dst[pinned_dst[e]], 1); break;
        case 5: atomicAdd(&g_cnt_connect_dst[connect_dst[e]], 1); break;
        case 6: atomicAdd(&g_cnt_pt_dst[pt_dst[e]], 1); break;
        case 7: atomicAdd(&g_cnt_pf_dst[pf_dst[e]], 1); break;
        case 8: {
            int b = pinned_src[e] >> 4;
            int s = atomicAdd(&g_bincnt_net[b], 1);
            if (s < CAPN) g_bin_net[b * CAPN + s] = e;
            break;
        }
        default: {
            int b = pf_src[e] >> 4;
            int s = atomicAdd(&g_bincnt_han[b], 1);
            if (s < CAPH) g_bin_han[b * CAPH + s] = e;
            break;
        }
    }
}

// GraphConv scatter: 8 threads/edge, float4 vector REDs. 3 edge sets.
__global__ void k_gc_scatter(const float* __restrict__ node_feat, const float* __restrict__ hanna_feat,
                             const int* __restrict__ pins_src, const int* __restrict__ pins_dst,
                             const int* __restrict__ connect_src, const int* __restrict__ connect_dst,
                             const int* __restrict__ pt_src, const int* __restrict__ pt_dst) {
    int gt = blockIdx.x * blockDim.x + threadIdx.x;
    int ge = gt >> 3;
    int j = gt & 7;
    if (ge >= 3 * NE) return;
    const float* feat; const int* srcA; const int* dstA; const int* cnt; float* agg; int e;
    if (ge < NE)          { e = ge;          feat = node_feat;  srcA = pins_src;    dstA = pins_dst;    cnt = g_cnt_pins_src;    agg = g_agg_net;   }
    else if (ge < 2 * NE) { e = ge - NE;     feat = hanna_feat; srcA = connect_src; dstA = connect_dst; cnt = g_cnt_connect_src; agg = g_agg_gc_c;  }
    else                  { e = ge - 2 * NE; feat = node_feat;  srcA = pt_src;      dstA = pt_dst;      cnt = g_cnt_pt_src;      agg = g_agg_gc_pt; }
    int s = srcA[e], d = dstA[e];
    float scale = rsqrtf((float)max(cnt[s], 1));
    float4 f = ((const float4*)(feat + (size_t)s * D))[j];
    f.x *= scale; f.y *= scale; f.z *= scale; f.w *= scale;
    red_add_f4(agg + (size_t)d * D + j * 4, f);
}

// Fused NNConv: block owns TSRC=16 consecutive source nodes (== one bin).
__global__ __launch_bounds__(544, 2) void k_nn(
        const float* __restrict__ net_feat, const float* __restrict__ hanna_feat,
        const float* __restrict__ W_topo, const float* __restrict__ b_topo,
        const float* __restrict__ pin_feat, const float* __restrict__ edge_feat,
        const int* __restrict__ pinned_src, const int* __restrict__ pinned_dst,
        const int* __restrict__ pf_src, const int* __restrict__ pf_dst) {
    __shared__ float4 sh_h4[TSRC * 8];            // 16 rows x 32 feats
    __shared__ float sh_G[TSRC * GP * D];         // 16 x 17 x 32 = 34.8 KB

    int bid = blockIdx.x;
    const float* h; const float* ef; const int* srcA; const int* dstA;
    const int* bins; const int* bincnt; float* agg; int first, cap, bin;
    if (bid < NB_NET_NN) {
        bin = bid; first = bid * TSRC;
        h = net_feat; ef = pin_feat; srcA = pinned_src; dstA = pinned_dst;
        bins = g_bin_net; bincnt = g_bincnt_net; agg = g_agg_cell_pd; cap = CAPN;
    } else {
        bin = bid - NB_NET_NN; first = bin * TSRC;
        h = hanna_feat; ef = edge_feat; srcA = pf_src; dstA = pf_dst;
        bins = g_bin_han; bincnt = g_bincnt_han; agg = g_agg_cell_pf; cap = CAPH;
    }
    int tid = threadIdx.x;

    if (tid < TSRC * D) ((float*)sh_h4)[tid] = h[(size_t)first * D + tid];
    __syncthreads();

    // ---- phase 1: G compute (thread = (p, o), 16 accumulators) ----
    {
        int p = tid >> 5, o = tid & 31;
        const float* w = ((p < DPF) ? (W_topo + p * (D * D)) : b_topo) + o;
        float acc[TSRC];
#pragma unroll
        for (int t = 0; t < TSRC; t++) acc[t] = 0.f;
#pragma unroll
        for (int i4 = 0; i4 < 8; i4++) {
            float w0 = w[(i4 * 4 + 0) * D];
            float w1 = w[(i4 * 4 + 1) * D];
            float w2 = w[(i4 * 4 + 2) * D];
            float w3 = w[(i4 * 4 + 3) * D];
#pragma unroll
            for (int t = 0; t < TSRC; t++) {
                float4 h4 = sh_h4[t * 8 + i4];
                acc[t] = fmaf(h4.x, w0, fmaf(h4.y, w1, fmaf(h4.z, w2, fmaf(h4.w, w3, acc[t]))));
            }
        }
#pragma unroll
        for (int t = 0; t < TSRC; t++) sh_G[t * (GP * D) + p * D + o] = acc[t];
    }
    __syncthreads();

    // ---- phase 2: edge streaming from this block's bin ----
    int bs = bin * cap;
    int nE = bincnt[bin];
    int grp = tid >> 3;        // 68 groups of 8
    int j8 = tid & 7;
    int iters = (nE + 67) / 68;
    for (int it = 0; it < iters; it++) {
        int j = it * 68 + grp;
        bool valid = j < nE;
        int eid = bins[bs + (valid ? j : 0)];
        int s = srcA[eid];
        int t = s - first;
        int d = dstA[eid];
        float2 c2 = ((const float2*)(ef + (size_t)eid * DPF))[j8];
        const float* Gt = sh_G + t * (GP * D);
        float4 a = {0.f, 0.f, 0.f, 0.f};
#pragma unroll
        for (int p = 0; p < GP; p++) {
            float cp;
            if (p < DPF) cp = __shfl_sync(0xffffffffu, (p & 1) ? c2.y : c2.x, p >> 1, 8);
            else cp = 1.f;
            float4 g4 = ((const float4*)(Gt + p * D))[j8];
            a.x = fmaf(cp, g4.x, a.x);
            a.y = fmaf(cp, g4.y, a.y);
            a.z = fmaf(cp, g4.z, a.z);
            a.w = fmaf(cp, g4.w, a.w);
        }
        if (valid) red_add_f4(agg + (size_t)d * D + j8 * 4, a);
    }
}

// merged epilogue: block ranges dispatch cell / net / gcell outputs
#define NBF_CELL ((N_CELL * D) / 256)   // 6250
#define NBF_NET  (N_NET / 8)            // 1250
#define NBF_GC   (N_GCELL / 8)          // 2500
__global__ void k_final(const float* __restrict__ net_feat,
                        const float* __restrict__ W_pins, const float* __restrict__ b_pins,
                        const float* __restrict__ W_net, const float* __restrict__ b_net,
                        const float* __restrict__ W_connect, const float* __restrict__ b_connect,
                        const float* __restrict__ W_pt, const float* __restrict__ b_pt,
                        const float* __restrict__ b_pinned, const float* __restrict__ b_pf,
                        float* __restrict__ out_cell, float* __restrict__ out_net,
                        float* __restrict__ out_gcell) {
    __shared__ float sW1[D * D], sW2[D * D];
    int b = blockIdx.x;
    if (b < NBF_CELL) {
        int idx = b * 256 + threadIdx.x;
        int c = idx >> 5, o = idx & 31;
        float d1 = (float)max(g_cnt_pinned_dst[c], 1);
        float d2 = (float)max(g_cnt_pf_dst[c], 1);
        out_cell[idx] = g_agg_cell_pd[idx] / d1 + b_pinned[o]
                      + g_agg_cell_pf[idx] / d2 + b_pf[o];
        return;
    }
    if (b < NBF_CELL + NBF_NET) {
        for (int i = threadIdx.x; i < D * D; i += 256) { sW1[i] = W_pins[i]; sW2[i] = W_net[i]; }
        __syncthreads();
        int n = (b - NBF_CELL) * 8 + (threadIdx.x >> 5);
        int o = threadIdx.x & 31;
        float acc = 0.f, acc2 = 0.f;
#pragma unroll
        for (int i = 0; i < D; i++) {
            acc  = fmaf(g_agg_net[n * D + i], sW1[i * D + o], acc);
            acc2 = fmaf(net_feat[n * D + i],  sW2[i * D + o], acc2);
        }
        float ddn = rsqrtf((float)max(g_cnt_pins_dst[n], 1));
        out_net[n * D + o] = acc * ddn + b_pins[o] + acc2 + b_net[o];
        return;
    }
    {
        for (int i = threadIdx.x; i < D * D; i += 256) { sW1[i] = W_connect[i]; sW2[i] = W_pt[i]; }
        __syncthreads();
        int g = (b - NBF_CELL - NBF_NET) * 8 + (threadIdx.x >> 5);
        int o = threadIdx.x & 31;
        float acc = 0.f, acc2 = 0.f;
#pragma unroll
        for (int i = 0; i < D; i++) {
            acc  = fmaf(g_agg_gc_c[g * D + i],  sW1[i * D + o], acc);
            acc2 = fmaf(g_agg_gc_pt[g * D + i], sW2[i * D + o], acc2);
        }
        float dc = rsqrtf((float)max(g_cnt_connect_dst[g], 1));
        float dp = rsqrtf((float)max(g_cnt_pt_dst[g], 1));
        out_gcell[g * D + o] = acc * dc + b_connect[o] + acc2 * dp + b_pt[o];
    }
}

// ---------------- launch ----------------

extern "C" void kernel_launch(void* const* d_in, const int* in_sizes, int n_in,
                              void* d_out, int out_size) {
    const float* node_feat   = (const float*)d_in[0];
    const float* net_feat    = (const float*)d_in[1];
    const float* pin_feat    = (const float*)d_in[2];
    const float* hanna_feat  = (const float*)d_in[3];
    const float* edge_feat   = (const float*)d_in[4];
    const int* pins_src      = (const int*)d_in[5];
    const int* pins_dst      = (const int*)d_in[6];
    const int* pinned_src    = (const int*)d_in[7];
    const int* pinned_dst    = (const int*)d_in[8];
    const int* connect_src   = (const int*)d_in[9];
    const int* connect_dst   = (const int*)d_in[10];
    const int* pt_src        = (const int*)d_in[11];
    const int* pt_dst        = (const int*)d_in[12];
    const int* pf_src        = (const int*)d_in[13];
    const int* pf_dst        = (const int*)d_in[14];
    const float* W_net       = (const float*)d_in[15];
    const float* b_net       = (const float*)d_in[16];
    const float* W_topo      = (const float*)d_in[17];
    const float* b_topo      = (const float*)d_in[18];
    const float* W_pins      = (const float*)d_in[19];
    const float* b_pins      = (const float*)d_in[20];
    const float* W_connect   = (const float*)d_in[21];
    const float* b_connect   = (const float*)d_in[22];
    const float* W_pt        = (const float*)d_in[23];
    const float* b_pt        = (const float*)d_in[24];
    const float* b_pinned    = (const float*)d_in[25];
    const float* b_pf        = (const float*)d_in[26];

    float* out       = (float*)d_out;
    float* out_cell  = out;
    float* out_net   = out + (size_t)N_CELL * D;
    float* out_gcell = out + (size_t)(N_CELL + N_NET) * D;

    // side stream + events for fork/join inside graph capture (created once; never freed)
    static cudaStream_t s1 = nullptr;
    static cudaEvent_t evP = nullptr, evNN = nullptr;
    if (s1 == nullptr) {
        cudaStreamCreateWithFlags(&s1, cudaStreamNonBlocking);
        cudaEventCreateWithFlags(&evP, cudaEventDisableTiming);
        cudaEventCreateWithFlags(&evNN, cudaEventDisableTiming);
    }

    // main: zero -> prep (all counts + bins in one wide kernel)
    k_zero<<<1024, 256>>>();
    k_prep<<<10 * RBLK, 256>>>(pins_src, pins_dst, pinned_src, pinned_dst,
                               connect_src, connect_dst, pt_src, pt_dst,
                               pf_src, pf_dst);
    cudaEventRecord(evP, 0);

    // s1: fused nnconv (waits on prep for bins)
    cudaStreamWaitEvent(s1, evP, 0);
    k_nn<<<NB_NET_NN + NB_GC_NN, 544, 0, s1>>>(net_feat, hanna_feat, W_topo, b_topo,
                                               pin_feat, edge_feat,
                                               pinned_src, pinned_dst, pf_src, pf_dst);
    cudaEventRecord(evNN, s1);

    // main: graphconv scatter (waits on prep for src counts), concurrent with k_nn
    k_gc_scatter<<<(3 * NE * 8 + 255) / 256, 256>>>(node_feat, hanna_feat,
                                                    pins_src, pins_dst,
                                                    connect_src, connect_dst,
                                                    pt_src, pt_dst);

    // join and finish
    cudaStreamWaitEvent(0, evNN, 0);
    k_final<<<NBF_CELL + NBF_NET + NBF_GC, 256>>>(net_feat, W_pins, b_pins, W_net, b_net,
                                                  W_connect, b_connect, W_pt, b_pt,
                                                  b_pinned, b_pf,
                                                  out_cell, out_net, out_gcell);
}